// round 7
// baseline (speedup 1.0000x reference)
#include <cuda_runtime.h>
#include <cuda_fp16.h>
#include <cstdint>
#include <math.h>

#define DIM      64
#define NREL     16
#define NCOLS    (NREL * DIM)        // 1024
#define MAX_N    120000
#define MAX_E    1600000

// ---- scratch ----
__device__ __align__(256) __half g_trans[(size_t)MAX_N * NCOLS];
__device__ __align__(256) float  g_ex[MAX_E];
__device__ __align__(256) float  g_denom[MAX_N];

__device__ __forceinline__ uint32_t smem_u32(const void* p) {
    uint32_t a;
    asm("{ .reg .u64 t; cvta.to.shared.u64 t, %1; cvt.u32.u64 %0, t; }"
        : "=r"(a) : "l"(p));
    return a;
}

// ---- warp-mma helpers (family-common PTX) ----
__device__ __forceinline__ void ldsm_x4(uint32_t addr, uint32_t* r) {
    asm volatile("ldmatrix.sync.aligned.m8n8.x4.shared.b16 {%0,%1,%2,%3}, [%4];"
        : "=r"(r[0]), "=r"(r[1]), "=r"(r[2]), "=r"(r[3]) : "r"(addr));
}
__device__ __forceinline__ void ldsm_x4_t(uint32_t addr, uint32_t* r) {
    asm volatile("ldmatrix.sync.aligned.m8n8.x4.trans.shared.b16 {%0,%1,%2,%3}, [%4];"
        : "=r"(r[0]), "=r"(r[1]), "=r"(r[2]), "=r"(r[3]) : "r"(addr));
}
__device__ __forceinline__ void mma_fp16(float* c, const uint32_t* a,
                                         uint32_t b0, uint32_t b1) {
    asm volatile(
        "mma.sync.aligned.m16n8k16.row.col.f32.f16.f16.f32 "
        "{%0,%1,%2,%3}, {%4,%5,%6,%7}, {%8,%9}, {%0,%1,%2,%3};"
        : "+f"(c[0]), "+f"(c[1]), "+f"(c[2]), "+f"(c[3])
        : "r"(a[0]), "r"(a[1]), "r"(a[2]), "r"(a[3]), "r"(b0), "r"(b1));
}

// smem: A (persistent, 16 KB) + B (8 KB) + OUT staging (16 KB)
#define SM_A    0
#define SM_B    (SM_A + 128 * 128)
#define SM_OUT  (SM_B + 64 * 128)
#define SM_TOT  (SM_OUT + 128 * 128)   // 40960 B

#define SWZ(row, colb) (((uint32_t)(row)) * 128u + (((uint32_t)(colb)) ^ ((((uint32_t)(row)) & 7u) << 4)))

// ---- K1: fp16 warp-MMA GEMM, relation loop inside CTA (A staged once) ----
__global__ __launch_bounds__(256)
void gemm_kernel(const float* __restrict__ emb, const float* __restrict__ W, int M)
{
    extern __shared__ char smem[];
    const uint32_t sb = smem_u32(smem);
    const int tid  = threadIdx.x;
    const int wid  = tid >> 5;
    const int lane = tid & 31;
    const int m0   = blockIdx.x * 128;

    // fused init of softmax denominators for this row range
    if (tid < 128) {
        int gm = m0 + tid;
        if (gm < M) g_denom[gm] = 0.0f;
    }

    // --- stage A once (128x64 fp32 -> fp16, swizzled) ---
    #pragma unroll
    for (int p = 0; p < 8; p++) {
        int idx = tid + p * 256;          // 0..2047
        int row = idx >> 4;
        int c4  = idx & 15;
        int gm  = m0 + row;
        float4 v = (gm < M) ? ((const float4*)(emb + (size_t)gm * DIM))[c4]
                            : make_float4(0.f, 0.f, 0.f, 0.f);
        __half2 h01 = __floats2half2_rn(v.x, v.y);
        __half2 h23 = __floats2half2_rn(v.z, v.w);
        *(uint2*)(smem + SM_A + SWZ(row, c4 * 8)) =
            make_uint2(*(uint32_t*)&h01, *(uint32_t*)&h23);
    }
    __syncthreads();

    // per-lane fragment address components
    const int wr = wid * 16;
    const int a_midx = lane >> 3, a_r = lane & 7;
    const int a_row  = wr + (a_midx & 1) * 8 + a_r;
    const int a_colb0 = (a_midx >> 1) * 16;
    const int b_i    = lane & 7, b_half = lane >> 3;
    const int b_krow0 = (b_half & 1) * 8 + b_i;
    const int b_ncol0 = (b_half >> 1) * 16;

    // --- load A fragments ONCE (relation-invariant) ---
    uint32_t afrag[4][4];
    #pragma unroll
    for (int ks = 0; ks < 4; ks++)
        ldsm_x4(sb + SM_A + SWZ(a_row, ks * 32 + a_colb0), afrag[ks]);

    const int rl0 = wr + (lane >> 2);
    const int rl1 = rl0 + 8;
    const int cbb = (lane & 3) * 4;

    for (int rrel = 0; rrel < NREL; rrel++) {
        const float* Wr = W + (size_t)rrel * (DIM * DIM);

        // stage B_r (64x64 fp32 -> fp16, swizzled). Safe: MMA of r-1 finished
        // before sync2(r-1); this runs after it.
        #pragma unroll
        for (int p = 0; p < 4; p++) {
            int idx = tid + p * 256;      // 0..1023 float4s
            int d  = idx >> 4;
            int c4 = idx & 15;
            float4 v = ((const float4*)Wr)[idx];
            __half2 h01 = __floats2half2_rn(v.x, v.y);
            __half2 h23 = __floats2half2_rn(v.z, v.w);
            *(uint2*)(smem + SM_B + SWZ(d, c4 * 8)) =
                make_uint2(*(uint32_t*)&h01, *(uint32_t*)&h23);
        }
        __syncthreads();   // B ready; prior copy-out of OUT done

        float c[8][4];
        #pragma unroll
        for (int t = 0; t < 8; t++)
            #pragma unroll
            for (int j = 0; j < 4; j++) c[t][j] = 0.0f;

        #pragma unroll
        for (int ks = 0; ks < 4; ks++) {
            #pragma unroll
            for (int np = 0; np < 4; np++) {
                uint32_t b[4];
                int krow = ks * 16 + b_krow0;
                ldsm_x4_t(sb + SM_B + SWZ(krow, np * 32 + b_ncol0), b);
                mma_fp16(c[np * 2 + 0], afrag[ks], b[0], b[1]);
                mma_fp16(c[np * 2 + 1], afrag[ks], b[2], b[3]);
            }
        }

        // stage fragments into OUT (fp16, swizzled)
        #pragma unroll
        for (int t = 0; t < 8; t++) {
            __half2 v0 = __floats2half2_rn(c[t][0], c[t][1]);
            __half2 v1 = __floats2half2_rn(c[t][2], c[t][3]);
            *(__half2*)(smem + SM_OUT + SWZ(rl0, cbb + t * 16)) = v0;
            *(__half2*)(smem + SM_OUT + SWZ(rl1, cbb + t * 16)) = v1;
        }
        __syncthreads();   // OUT staged

        // coalesced copy OUT -> g_trans (128 rows x 128 B)
        #pragma unroll
        for (int p = 0; p < 4; p++) {
            int idx  = tid + p * 256;     // 0..1023
            int row  = idx >> 3;
            int ch16 = idx & 7;
            int gm   = m0 + row;
            if (gm < M) {
                uint4 v = *(uint4*)(smem + SM_OUT + SWZ(row, ch16 * 16));
                *(uint4*)&g_trans[(size_t)gm * NCOLS + rrel * DIM + ch16 * 8] = v;
            }
        }
    }
}

// ---- K2: per-edge logit + exp + segment-sum (warp per edge; no max pass —
// logits here are tightly bounded, softmax is shift-invariant) ----
__global__ __launch_bounds__(256) void att_kernel(
    const int* __restrict__ src, const int* __restrict__ dst,
    const int* __restrict__ typ, const float* __restrict__ rel, int E)
{
    int gw   = (blockIdx.x * blockDim.x + threadIdx.x) >> 5;
    int lane = threadIdx.x & 31;
    if (gw >= E) return;

    int s = src[gw], d = dst[gw], r = typ[gw];
    const __half2* t  = (const __half2*)(g_trans + (size_t)s * NCOLS + r * DIM);
    const __half2* h  = (const __half2*)(g_trans + (size_t)d * NCOLS + r * DIM);
    const float2*  re = (const float2*)(rel + (size_t)r * DIM);

    float2 tv = __half22float2(t[lane]);
    float2 hv = __half22float2(h[lane]);
    float2 rv = re[lane];
    float p = tv.x * tanhf(hv.x + rv.x) + tv.y * tanhf(hv.y + rv.y);

    #pragma unroll
    for (int o = 16; o > 0; o >>= 1) p += __shfl_xor_sync(0xffffffffu, p, o);

    if (lane == 0) {
        float e = expf(p);
        g_ex[gw] = e;
        atomicAdd(&g_denom[d], e);
    }
}

// ---- K3: normalize ----
__global__ void norm_kernel(const int* __restrict__ dst, float* __restrict__ out, int E) {
    int i = blockIdx.x * blockDim.x + threadIdx.x;
    if (i < E) out[i] = g_ex[i] / g_denom[dst[i]];
}

extern "C" void kernel_launch(void* const* d_in, const int* in_sizes, int n_in,
                              void* d_out, int out_size)
{
    const float* emb = (const float*)d_in[0];
    const float* rel = (const float*)d_in[1];
    const float* W   = (const float*)d_in[2];
    const int*   src = (const int*)d_in[3];
    const int*   dst = (const int*)d_in[4];
    const int*   typ = (const int*)d_in[5];
    float*       out = (float*)d_out;

    int M = in_sizes[0] / DIM;
    int E = in_sizes[3];

    static bool attr_set = false;
    if (!attr_set) {
        cudaFuncSetAttribute(gemm_kernel,
                             cudaFuncAttributeMaxDynamicSharedMemorySize, SM_TOT);
        attr_set = true;
    }

    gemm_kernel<<<(M + 127) / 128, 256, SM_TOT>>>(emb, W, M);
    att_kernel<<<(E + 7) / 8, 256>>>(src, dst, typ, rel, E);
    norm_kernel<<<(E + 255) / 256, 256>>>(dst, out, E);
}

// round 8
// speedup vs baseline: 1.7155x; 1.7155x over previous
#include <cuda_runtime.h>
#include <cuda_fp16.h>
#include <cstdint>
#include <math.h>

#define DIM      64
#define NREL     16
#define NCOLS    (NREL * DIM)        // 1024
#define MAX_N    120000
#define MAX_E    1600000

// ---- scratch ----
__device__ __align__(256) __half g_trans[(size_t)MAX_N * NCOLS];
__device__ __align__(256) float  g_ex[MAX_E];
__device__ __align__(256) float  g_denom[MAX_N];

__device__ __forceinline__ uint32_t smem_u32(const void* p) {
    uint32_t a;
    asm("{ .reg .u64 t; cvta.to.shared.u64 t, %1; cvt.u32.u64 %0, t; }"
        : "=r"(a) : "l"(p));
    return a;
}
__device__ __forceinline__ float tanha(float x) {
    float y;
    asm("tanh.approx.f32 %0, %1;" : "=f"(y) : "f"(x));
    return y;
}

// ---- warp-mma helpers (family-common PTX) ----
__device__ __forceinline__ void ldsm_x4(uint32_t addr, uint32_t* r) {
    asm volatile("ldmatrix.sync.aligned.m8n8.x4.shared.b16 {%0,%1,%2,%3}, [%4];"
        : "=r"(r[0]), "=r"(r[1]), "=r"(r[2]), "=r"(r[3]) : "r"(addr));
}
__device__ __forceinline__ void ldsm_x4_t(uint32_t addr, uint32_t* r) {
    asm volatile("ldmatrix.sync.aligned.m8n8.x4.trans.shared.b16 {%0,%1,%2,%3}, [%4];"
        : "=r"(r[0]), "=r"(r[1]), "=r"(r[2]), "=r"(r[3]) : "r"(addr));
}
__device__ __forceinline__ void mma_fp16(float* c, const uint32_t* a,
                                         uint32_t b0, uint32_t b1) {
    asm volatile(
        "mma.sync.aligned.m16n8k16.row.col.f32.f16.f16.f32 "
        "{%0,%1,%2,%3}, {%4,%5,%6,%7}, {%8,%9}, {%0,%1,%2,%3};"
        : "+f"(c[0]), "+f"(c[1]), "+f"(c[2]), "+f"(c[3])
        : "r"(a[0]), "r"(a[1]), "r"(a[2]), "r"(a[3]), "r"(b0), "r"(b1));
}

// smem: A (persistent, 16 KB) + B (8 KB) + OUT staging (16 KB)
#define SM_A    0
#define SM_B    (SM_A + 128 * 128)
#define SM_OUT  (SM_B + 64 * 128)
#define SM_TOT  (SM_OUT + 128 * 128)   // 40960 B

#define SWZ(row, colb) (((uint32_t)(row)) * 128u + (((uint32_t)(colb)) ^ ((((uint32_t)(row)) & 7u) << 4)))

// ---- K1: fp16 warp-MMA GEMM, relation loop inside CTA (A staged once) ----
__global__ __launch_bounds__(256)
void gemm_kernel(const float* __restrict__ emb, const float* __restrict__ W, int M)
{
    extern __shared__ char smem[];
    const uint32_t sb = smem_u32(smem);
    const int tid  = threadIdx.x;
    const int wid  = tid >> 5;
    const int lane = tid & 31;
    const int m0   = blockIdx.x * 128;

    if (tid < 128) {
        int gm = m0 + tid;
        if (gm < M) g_denom[gm] = 0.0f;
    }

    // --- stage A once (128x64 fp32 -> fp16, swizzled) ---
    #pragma unroll
    for (int p = 0; p < 8; p++) {
        int idx = tid + p * 256;
        int row = idx >> 4;
        int c4  = idx & 15;
        int gm  = m0 + row;
        float4 v = (gm < M) ? ((const float4*)(emb + (size_t)gm * DIM))[c4]
                            : make_float4(0.f, 0.f, 0.f, 0.f);
        __half2 h01 = __floats2half2_rn(v.x, v.y);
        __half2 h23 = __floats2half2_rn(v.z, v.w);
        *(uint2*)(smem + SM_A + SWZ(row, c4 * 8)) =
            make_uint2(*(uint32_t*)&h01, *(uint32_t*)&h23);
    }
    __syncthreads();

    const int wr = wid * 16;
    const int a_midx = lane >> 3, a_r = lane & 7;
    const int a_row  = wr + (a_midx & 1) * 8 + a_r;
    const int a_colb0 = (a_midx >> 1) * 16;
    const int b_i    = lane & 7, b_half = lane >> 3;
    const int b_krow0 = (b_half & 1) * 8 + b_i;
    const int b_ncol0 = (b_half >> 1) * 16;

    uint32_t afrag[4][4];
    #pragma unroll
    for (int ks = 0; ks < 4; ks++)
        ldsm_x4(sb + SM_A + SWZ(a_row, ks * 32 + a_colb0), afrag[ks]);

    const int rl0 = wr + (lane >> 2);
    const int rl1 = rl0 + 8;
    const int cbb = (lane & 3) * 4;

    for (int rrel = 0; rrel < NREL; rrel++) {
        const float* Wr = W + (size_t)rrel * (DIM * DIM);

        #pragma unroll
        for (int p = 0; p < 4; p++) {
            int idx = tid + p * 256;
            int d  = idx >> 4;
            int c4 = idx & 15;
            float4 v = ((const float4*)Wr)[idx];
            __half2 h01 = __floats2half2_rn(v.x, v.y);
            __half2 h23 = __floats2half2_rn(v.z, v.w);
            *(uint2*)(smem + SM_B + SWZ(d, c4 * 8)) =
                make_uint2(*(uint32_t*)&h01, *(uint32_t*)&h23);
        }
        __syncthreads();

        float c[8][4];
        #pragma unroll
        for (int t = 0; t < 8; t++)
            #pragma unroll
            for (int j = 0; j < 4; j++) c[t][j] = 0.0f;

        #pragma unroll
        for (int ks = 0; ks < 4; ks++) {
            #pragma unroll
            for (int np = 0; np < 4; np++) {
                uint32_t b[4];
                int krow = ks * 16 + b_krow0;
                ldsm_x4_t(sb + SM_B + SWZ(krow, np * 32 + b_ncol0), b);
                mma_fp16(c[np * 2 + 0], afrag[ks], b[0], b[1]);
                mma_fp16(c[np * 2 + 1], afrag[ks], b[2], b[3]);
            }
        }

        #pragma unroll
        for (int t = 0; t < 8; t++) {
            __half2 v0 = __floats2half2_rn(c[t][0], c[t][1]);
            __half2 v1 = __floats2half2_rn(c[t][2], c[t][3]);
            *(__half2*)(smem + SM_OUT + SWZ(rl0, cbb + t * 16)) = v0;
            *(__half2*)(smem + SM_OUT + SWZ(rl1, cbb + t * 16)) = v1;
        }
        __syncthreads();

        #pragma unroll
        for (int p = 0; p < 4; p++) {
            int idx  = tid + p * 256;
            int row  = idx >> 3;
            int ch16 = idx & 7;
            int gm   = m0 + row;
            if (gm < M) {
                uint4 v = *(uint4*)(smem + SM_OUT + SWZ(row, ch16 * 16));
                *(uint4*)&g_trans[(size_t)gm * NCOLS + rrel * DIM + ch16 * 8] = v;
            }
        }
    }
}

// ---- K2: per-edge logit + exp + segment-sum.
// 8 lanes per edge, 4 edges per warp. HW tanh. rel table in smem. ----
__global__ __launch_bounds__(256) void att_kernel(
    const int* __restrict__ src, const int* __restrict__ dst,
    const int* __restrict__ typ, const float* __restrict__ rel, int E)
{
    __shared__ float s_rel[NREL * DIM];   // 4 KB
    const int tid = threadIdx.x;
    #pragma unroll
    for (int i = tid; i < NREL * DIM; i += 256) s_rel[i] = rel[i];
    __syncthreads();

    const int lane = tid & 31;
    const int grp  = lane >> 3;           // edge within warp: 0..3
    const int sub  = lane & 7;            // lane within edge: 0..7
    const int warp = (blockIdx.x * 256 + tid) >> 5;
    const int e    = warp * 4 + grp;
    const bool valid = (e < E);

    int s = 0, d = 0, r = 0;
    if (valid) { s = src[e]; d = dst[e]; r = typ[e]; }

    float p = 0.0f;
    if (valid) {
        const __half* tp = g_trans + (size_t)s * NCOLS + r * DIM + sub * 8;
        const __half* hp = g_trans + (size_t)d * NCOLS + r * DIM + sub * 8;
        uint4 tv4 = *(const uint4*)tp;     // 8 halfs
        uint4 hv4 = *(const uint4*)hp;
        const float* rr = &s_rel[r * DIM + sub * 8];
        float4 r03 = *(const float4*)(rr);
        float4 r47 = *(const float4*)(rr + 4);
        const float* rv = &r03.x;          // 8 consecutive floats via two float4s

        const uint32_t* tw = (const uint32_t*)&tv4;
        const uint32_t* hw = (const uint32_t*)&hv4;
        float rvs[8] = { r03.x, r03.y, r03.z, r03.w, r47.x, r47.y, r47.z, r47.w };
        (void)rv;
        #pragma unroll
        for (int j = 0; j < 4; j++) {
            float2 tf = __half22float2(*(const __half2*)&tw[j]);
            float2 hf = __half22float2(*(const __half2*)&hw[j]);
            p += tf.x * tanha(hf.x + rvs[2 * j]);
            p += tf.y * tanha(hf.y + rvs[2 * j + 1]);
        }
    }
    // reduce across the 8 lanes of this edge (xor 1,2,4 stays in-group)
    p += __shfl_xor_sync(0xffffffffu, p, 1);
    p += __shfl_xor_sync(0xffffffffu, p, 2);
    p += __shfl_xor_sync(0xffffffffu, p, 4);

    if (valid && sub == 0) {
        float ex = __expf(p);
        g_ex[e] = ex;
        atomicAdd(&g_denom[d], ex);
    }
}

// ---- K3: normalize ----
__global__ void norm_kernel(const int* __restrict__ dst, float* __restrict__ out, int E) {
    int i = blockIdx.x * blockDim.x + threadIdx.x;
    if (i < E) out[i] = g_ex[i] / g_denom[dst[i]];
}

extern "C" void kernel_launch(void* const* d_in, const int* in_sizes, int n_in,
                              void* d_out, int out_size)
{
    const float* emb = (const float*)d_in[0];
    const float* rel = (const float*)d_in[1];
    const float* W   = (const float*)d_in[2];
    const int*   src = (const int*)d_in[3];
    const int*   dst = (const int*)d_in[4];
    const int*   typ = (const int*)d_in[5];
    float*       out = (float*)d_out;

    int M = in_sizes[0] / DIM;
    int E = in_sizes[3];

    static bool attr_set = false;
    if (!attr_set) {
        cudaFuncSetAttribute(gemm_kernel,
                             cudaFuncAttributeMaxDynamicSharedMemorySize, SM_TOT);
        attr_set = true;
    }

    gemm_kernel<<<(M + 127) / 128, 256, SM_TOT>>>(emb, W, M);
    att_kernel<<<(E + 31) / 32, 256>>>(src, dst, typ, rel, E);   // 32 edges / 256-thr block
    norm_kernel<<<(E + 255) / 256, 256>>>(dst, out, E);
}

// round 9
// speedup vs baseline: 1.8225x; 1.0624x over previous
#include <cuda_runtime.h>
#include <cuda_fp16.h>
#include <cstdint>
#include <math.h>

#define DIM      64
#define NREL     16
#define NCOLS    (NREL * DIM)        // 1024
#define MAX_N    120000
#define MAX_E    1600000

// ---- scratch ----
__device__ __align__(256) __half g_trans[(size_t)MAX_N * NCOLS];
__device__ __align__(256) float  g_ex[MAX_E];
__device__ __align__(256) float  g_denom[MAX_N];

__device__ __forceinline__ uint32_t smem_u32(const void* p) {
    uint32_t a;
    asm("{ .reg .u64 t; cvta.to.shared.u64 t, %1; cvt.u32.u64 %0, t; }"
        : "=r"(a) : "l"(p));
    return a;
}
__device__ __forceinline__ float tanha(float x) {
    float y;
    asm("tanh.approx.f32 %0, %1;" : "=f"(y) : "f"(x));
    return y;
}

// ---- warp-mma helpers ----
__device__ __forceinline__ void ldsm_x4(uint32_t addr, uint32_t* r) {
    asm volatile("ldmatrix.sync.aligned.m8n8.x4.shared.b16 {%0,%1,%2,%3}, [%4];"
        : "=r"(r[0]), "=r"(r[1]), "=r"(r[2]), "=r"(r[3]) : "r"(addr));
}
__device__ __forceinline__ void ldsm_x4_t(uint32_t addr, uint32_t* r) {
    asm volatile("ldmatrix.sync.aligned.m8n8.x4.trans.shared.b16 {%0,%1,%2,%3}, [%4];"
        : "=r"(r[0]), "=r"(r[1]), "=r"(r[2]), "=r"(r[3]) : "r"(addr));
}
__device__ __forceinline__ void mma_fp16(float* c, const uint32_t* a,
                                         uint32_t b0, uint32_t b1) {
    asm volatile(
        "mma.sync.aligned.m16n8k16.row.col.f32.f16.f16.f32 "
        "{%0,%1,%2,%3}, {%4,%5,%6,%7}, {%8,%9}, {%0,%1,%2,%3};"
        : "+f"(c[0]), "+f"(c[1]), "+f"(c[2]), "+f"(c[3])
        : "r"(a[0]), "r"(a[1]), "r"(a[2]), "r"(a[3]), "r"(b0), "r"(b1));
}

// smem: A (16 KB) + B double buffer (2 x 8 KB) = 32 KB
#define SM_A    0
#define SM_B    (SM_A + 128 * 128)
#define SM_TOT  (SM_B + 2 * 64 * 128)   // 32768 B

#define SWZ(row, colb) (((uint32_t)(row)) * 128u + (((uint32_t)(colb)) ^ ((((uint32_t)(row)) & 7u) << 4)))

// ---- K1: fp16 warp-MMA GEMM; warp tile 32x32; B double-buffered; direct epilogue ----
__global__ __launch_bounds__(256)
void gemm_kernel(const float* __restrict__ emb, const float* __restrict__ W, int M)
{
    extern __shared__ char smem[];
    const uint32_t sb = smem_u32(smem);
    const int tid  = threadIdx.x;
    const int wid  = tid >> 5;
    const int lane = tid & 31;
    const int m0   = blockIdx.x * 128;

    if (tid < 128) {
        int gm = m0 + tid;
        if (gm < M) g_denom[gm] = 0.0f;
    }

    // --- stage A once (128x64 fp32 -> fp16, swizzled) ---
    #pragma unroll
    for (int p = 0; p < 8; p++) {
        int idx = tid + p * 256;
        int row = idx >> 4;
        int c4  = idx & 15;
        int gm  = m0 + row;
        float4 v = (gm < M) ? ((const float4*)(emb + (size_t)gm * DIM))[c4]
                            : make_float4(0.f, 0.f, 0.f, 0.f);
        __half2 h01 = __floats2half2_rn(v.x, v.y);
        __half2 h23 = __floats2half2_rn(v.z, v.w);
        *(uint2*)(smem + SM_A + SWZ(row, c4 * 8)) =
            make_uint2(*(uint32_t*)&h01, *(uint32_t*)&h23);
    }

    // --- stage B for relation 0 into buffer 0 ---
    #pragma unroll
    for (int p = 0; p < 4; p++) {
        int idx = tid + p * 256;
        int d  = idx >> 4;
        int c4 = idx & 15;
        float4 v = ((const float4*)W)[idx];
        __half2 h01 = __floats2half2_rn(v.x, v.y);
        __half2 h23 = __floats2half2_rn(v.z, v.w);
        *(uint2*)(smem + SM_B + SWZ(d, c4 * 8)) =
            make_uint2(*(uint32_t*)&h01, *(uint32_t*)&h23);
    }
    __syncthreads();

    // warp grid: 4 row strips x 2 col strips
    const int wrow = (wid & 3) * 32;
    const int wcol = (wid >> 2) * 32;

    // ldmatrix lane address components
    const int a_midx = lane >> 3, a_r = lane & 7;
    const int a_colb0 = (a_midx >> 1) * 16;
    const int b_i = lane & 7, b_half = lane >> 3;
    const int b_krow0 = (b_half & 1) * 8 + b_i;
    const int b_ncol0 = (b_half >> 1) * 16;

    // --- A fragments once: 2 m-tiles x 4 k-steps ---
    uint32_t afrag[4][2][4];
    #pragma unroll
    for (int ks = 0; ks < 4; ks++)
        #pragma unroll
        for (int mt = 0; mt < 2; mt++) {
            int arow = wrow + mt * 16 + (a_midx & 1) * 8 + a_r;
            ldsm_x4(sb + SM_A + SWZ(arow, ks * 32 + a_colb0), afrag[ks][mt]);
        }

    const int er0 = (lane >> 2);       // fragment row within 8
    const int ecb = (lane & 3) * 2;    // fragment col pair

    for (int rrel = 0; rrel < NREL; rrel++) {
        const int cur = rrel & 1;
        const uint32_t bbuf = sb + SM_B + cur * 8192;

        // stage next relation's B into the other buffer (overlaps MMA)
        if (rrel + 1 < NREL) {
            const float* Wn = W + (size_t)(rrel + 1) * (DIM * DIM);
            char* nb = smem + SM_B + (1 - cur) * 8192;
            #pragma unroll
            for (int p = 0; p < 4; p++) {
                int idx = tid + p * 256;
                int d  = idx >> 4;
                int c4 = idx & 15;
                float4 v = ((const float4*)Wn)[idx];
                __half2 h01 = __floats2half2_rn(v.x, v.y);
                __half2 h23 = __floats2half2_rn(v.z, v.w);
                *(uint2*)(nb + SWZ(d, c4 * 8)) =
                    make_uint2(*(uint32_t*)&h01, *(uint32_t*)&h23);
            }
        }

        float c[2][4][4];
        #pragma unroll
        for (int mt = 0; mt < 2; mt++)
            #pragma unroll
            for (int nt = 0; nt < 4; nt++)
                #pragma unroll
                for (int j = 0; j < 4; j++) c[mt][nt][j] = 0.0f;

        #pragma unroll
        for (int ks = 0; ks < 4; ks++) {
            #pragma unroll
            for (int n2 = 0; n2 < 2; n2++) {      // two 16-col groups
                uint32_t b[4];
                int krow = ks * 16 + b_krow0;
                int colb = (wcol + n2 * 16) * 2 + b_ncol0;
                ldsm_x4_t(bbuf + SWZ(krow, colb), b);
                #pragma unroll
                for (int mt = 0; mt < 2; mt++) {
                    mma_fp16(c[mt][n2 * 2 + 0], afrag[ks][mt], b[0], b[1]);
                    mma_fp16(c[mt][n2 * 2 + 1], afrag[ks][mt], b[2], b[3]);
                }
            }
        }

        // --- direct epilogue: half2 stores; n-tiles fill sectors via L2 combining ---
        #pragma unroll
        for (int mt = 0; mt < 2; mt++) {
            int r0 = m0 + wrow + mt * 16 + er0;
            __half* base0 = &g_trans[(size_t)r0 * NCOLS + rrel * DIM + wcol + ecb];
            __half* base1 = base0 + (size_t)8 * NCOLS;
            if (r0 < M) {
                #pragma unroll
                for (int nt = 0; nt < 4; nt++)
                    *(__half2*)(base0 + nt * 8) = __floats2half2_rn(c[mt][nt][0], c[mt][nt][1]);
            }
            if (r0 + 8 < M) {
                #pragma unroll
                for (int nt = 0; nt < 4; nt++)
                    *(__half2*)(base1 + nt * 8) = __floats2half2_rn(c[mt][nt][2], c[mt][nt][3]);
            }
        }
        __syncthreads();   // next buffer fully staged before it becomes current
    }
}

// ---- K2: per-edge logit + exp + segment-sum (8 lanes/edge, HW tanh) ----
__global__ __launch_bounds__(256) void att_kernel(
    const int* __restrict__ src, const int* __restrict__ dst,
    const int* __restrict__ typ, const float* __restrict__ rel, int E)
{
    __shared__ float s_rel[NREL * DIM];
    const int tid = threadIdx.x;
    #pragma unroll
    for (int i = tid; i < NREL * DIM; i += 256) s_rel[i] = rel[i];
    __syncthreads();

    const int lane = tid & 31;
    const int grp  = lane >> 3;
    const int sub  = lane & 7;
    const int warp = (blockIdx.x * 256 + tid) >> 5;
    const int e    = warp * 4 + grp;
    const bool valid = (e < E);

    int s = 0, d = 0, r = 0;
    if (valid) { s = src[e]; d = dst[e]; r = typ[e]; }

    float p = 0.0f;
    if (valid) {
        const __half* tp = g_trans + (size_t)s * NCOLS + r * DIM + sub * 8;
        const __half* hp = g_trans + (size_t)d * NCOLS + r * DIM + sub * 8;
        uint4 tv4 = *(const uint4*)tp;
        uint4 hv4 = *(const uint4*)hp;
        const float* rr = &s_rel[r * DIM + sub * 8];
        float4 r03 = *(const float4*)(rr);
        float4 r47 = *(const float4*)(rr + 4);

        const uint32_t* tw = (const uint32_t*)&tv4;
        const uint32_t* hw = (const uint32_t*)&hv4;
        float rvs[8] = { r03.x, r03.y, r03.z, r03.w, r47.x, r47.y, r47.z, r47.w };
        #pragma unroll
        for (int j = 0; j < 4; j++) {
            float2 tf = __half22float2(*(const __half2*)&tw[j]);
            float2 hf = __half22float2(*(const __half2*)&hw[j]);
            p += tf.x * tanha(hf.x + rvs[2 * j]);
            p += tf.y * tanha(hf.y + rvs[2 * j + 1]);
        }
    }
    p += __shfl_xor_sync(0xffffffffu, p, 1);
    p += __shfl_xor_sync(0xffffffffu, p, 2);
    p += __shfl_xor_sync(0xffffffffu, p, 4);

    if (valid && sub == 0) {
        float ex = __expf(p);
        g_ex[e] = ex;
        atomicAdd(&g_denom[d], ex);
    }
}

// ---- K3: normalize ----
__global__ void norm_kernel(const int* __restrict__ dst, float* __restrict__ out, int E) {
    int i = blockIdx.x * blockDim.x + threadIdx.x;
    if (i < E) out[i] = g_ex[i] / g_denom[dst[i]];
}

extern "C" void kernel_launch(void* const* d_in, const int* in_sizes, int n_in,
                              void* d_out, int out_size)
{
    const float* emb = (const float*)d_in[0];
    const float* rel = (const float*)d_in[1];
    const float* W   = (const float*)d_in[2];
    const int*   src = (const int*)d_in[3];
    const int*   dst = (const int*)d_in[4];
    const int*   typ = (const int*)d_in[5];
    float*       out = (float*)d_out;

    int M = in_sizes[0] / DIM;
    int E = in_sizes[3];

    static bool attr_set = false;
    if (!attr_set) {
        cudaFuncSetAttribute(gemm_kernel,
                             cudaFuncAttributeMaxDynamicSharedMemorySize, SM_TOT);
        attr_set = true;
    }

    gemm_kernel<<<(M + 127) / 128, 256, SM_TOT>>>(emb, W, M);
    att_kernel<<<(E + 31) / 32, 256>>>(src, dst, typ, rel, E);
    norm_kernel<<<(E + 255) / 256, 256>>>(dst, out, E);
}

// round 10
// speedup vs baseline: 2.1747x; 1.1932x over previous
#include <cuda_runtime.h>
#include <cuda_fp16.h>
#include <cstdint>
#include <math.h>

#define DIM      64
#define NREL     16
#define NCOLS    (NREL * DIM)        // 1024
#define MAX_N    120000
#define MAX_E    1600000

// ---- scratch ----
__device__ __align__(256) __half g_trans[(size_t)MAX_N * NCOLS];
__device__ __align__(256) float  g_ex[MAX_E];
__device__ __align__(256) float  g_denom[MAX_N];

__device__ __forceinline__ uint32_t smem_u32(const void* p) {
    uint32_t a;
    asm("{ .reg .u64 t; cvta.to.shared.u64 t, %1; cvt.u32.u64 %0, t; }"
        : "=r"(a) : "l"(p));
    return a;
}
__device__ __forceinline__ float tanha(float x) {
    float y;
    asm("tanh.approx.f32 %0, %1;" : "=f"(y) : "f"(x));
    return y;
}

// ---- warp-mma helpers (family-common PTX) ----
__device__ __forceinline__ void ldsm_x4(uint32_t addr, uint32_t* r) {
    asm volatile("ldmatrix.sync.aligned.m8n8.x4.shared.b16 {%0,%1,%2,%3}, [%4];"
        : "=r"(r[0]), "=r"(r[1]), "=r"(r[2]), "=r"(r[3]) : "r"(addr));
}
__device__ __forceinline__ void ldsm_x4_t(uint32_t addr, uint32_t* r) {
    asm volatile("ldmatrix.sync.aligned.m8n8.x4.trans.shared.b16 {%0,%1,%2,%3}, [%4];"
        : "=r"(r[0]), "=r"(r[1]), "=r"(r[2]), "=r"(r[3]) : "r"(addr));
}
__device__ __forceinline__ void stsm_x4(uint32_t addr, uint32_t r0, uint32_t r1,
                                        uint32_t r2, uint32_t r3) {
    asm volatile("stmatrix.sync.aligned.m8n8.x4.shared.b16 [%0], {%1,%2,%3,%4};"
        :: "r"(addr), "r"(r0), "r"(r1), "r"(r2), "r"(r3) : "memory");
}
__device__ __forceinline__ void mma_fp16(float* c, const uint32_t* a,
                                         uint32_t b0, uint32_t b1) {
    asm volatile(
        "mma.sync.aligned.m16n8k16.row.col.f32.f16.f16.f32 "
        "{%0,%1,%2,%3}, {%4,%5,%6,%7}, {%8,%9}, {%0,%1,%2,%3};"
        : "+f"(c[0]), "+f"(c[1]), "+f"(c[2]), "+f"(c[3])
        : "r"(a[0]), "r"(a[1]), "r"(a[2]), "r"(a[3]), "r"(b0), "r"(b1));
}

// smem: A (16 KB) + B double buffer (2x8 KB) + OUT (16 KB) = 48 KB
#define SM_A    0
#define SM_B    (SM_A + 128 * 128)
#define SM_OUT  (SM_B + 2 * 64 * 128)
#define SM_TOT  (SM_OUT + 128 * 128)   // 49152 B

#define SWZ(row, colb) (((uint32_t)(row)) * 128u + (((uint32_t)(colb)) ^ ((((uint32_t)(row)) & 7u) << 4)))

// ---- K1: fp16 warp-MMA GEMM; 32x32 warp tiles; stmatrix epilogue; 3 CTA/SM ----
__global__ __launch_bounds__(256, 3)
void gemm_kernel(const float* __restrict__ emb, const float* __restrict__ W, int M)
{
    extern __shared__ char smem[];
    const uint32_t sb = smem_u32(smem);
    const int tid  = threadIdx.x;
    const int wid  = tid >> 5;
    const int lane = tid & 31;
    const int m0   = blockIdx.x * 128;

    if (tid < 128) {
        int gm = m0 + tid;
        if (gm < M) g_denom[gm] = 0.0f;
    }

    // --- stage A once (128x64 fp32 -> fp16, swizzled) ---
    #pragma unroll
    for (int p = 0; p < 8; p++) {
        int idx = tid + p * 256;
        int row = idx >> 4;
        int c4  = idx & 15;
        int gm  = m0 + row;
        float4 v = (gm < M) ? ((const float4*)(emb + (size_t)gm * DIM))[c4]
                            : make_float4(0.f, 0.f, 0.f, 0.f);
        __half2 h01 = __floats2half2_rn(v.x, v.y);
        __half2 h23 = __floats2half2_rn(v.z, v.w);
        *(uint2*)(smem + SM_A + SWZ(row, c4 * 8)) =
            make_uint2(*(uint32_t*)&h01, *(uint32_t*)&h23);
    }
    // --- stage B for relation 0 into buffer 0 ---
    #pragma unroll
    for (int p = 0; p < 4; p++) {
        int idx = tid + p * 256;
        int d  = idx >> 4;
        int c4 = idx & 15;
        float4 v = ((const float4*)W)[idx];
        __half2 h01 = __floats2half2_rn(v.x, v.y);
        __half2 h23 = __floats2half2_rn(v.z, v.w);
        *(uint2*)(smem + SM_B + SWZ(d, c4 * 8)) =
            make_uint2(*(uint32_t*)&h01, *(uint32_t*)&h23);
    }
    __syncthreads();

    // warp grid: 4 row strips x 2 col strips
    const int wrow = (wid & 3) * 32;
    const int wcol = (wid >> 2) * 32;

    const int a_midx = lane >> 3, a_r = lane & 7;
    const int a_colb0 = (a_midx >> 1) * 16;
    const int b_i = lane & 7, b_half = lane >> 3;
    const int b_krow0 = (b_half & 1) * 8 + b_i;
    const int b_ncol0 = (b_half >> 1) * 16;

    // stmatrix lane address (per warp, relation-invariant): tile g = lane>>3
    const uint32_t st_addr0 = sb + SM_OUT +
        SWZ(wrow + (lane & 7), (wcol + (lane >> 3) * 8) * 2);

    for (int rrel = 0; rrel < NREL; rrel++) {
        const int cur = rrel & 1;
        const uint32_t bbuf = sb + SM_B + cur * 8192;

        // stage next relation's B into the other buffer (overlaps MMA)
        if (rrel + 1 < NREL) {
            const float* Wn = W + (size_t)(rrel + 1) * (DIM * DIM);
            char* nb = smem + SM_B + (1 - cur) * 8192;
            #pragma unroll
            for (int p = 0; p < 4; p++) {
                int idx = tid + p * 256;
                int d  = idx >> 4;
                int c4 = idx & 15;
                float4 v = ((const float4*)Wn)[idx];
                __half2 h01 = __floats2half2_rn(v.x, v.y);
                __half2 h23 = __floats2half2_rn(v.z, v.w);
                *(uint2*)(nb + SWZ(d, c4 * 8)) =
                    make_uint2(*(uint32_t*)&h01, *(uint32_t*)&h23);
            }
        }

        float c[2][4][4];
        #pragma unroll
        for (int mt = 0; mt < 2; mt++)
            #pragma unroll
            for (int nt = 0; nt < 4; nt++)
                #pragma unroll
                for (int j = 0; j < 4; j++) c[mt][nt][j] = 0.0f;

        #pragma unroll
        for (int ks = 0; ks < 4; ks++) {
            // reload A fragments for this k-step (saves 24 regs vs persistent)
            uint32_t a0[4], a1[4];
            {
                int ar0 = wrow + (a_midx & 1) * 8 + a_r;
                ldsm_x4(sb + SM_A + SWZ(ar0,      ks * 32 + a_colb0), a0);
                ldsm_x4(sb + SM_A + SWZ(ar0 + 16, ks * 32 + a_colb0), a1);
            }
            #pragma unroll
            for (int n2 = 0; n2 < 2; n2++) {
                uint32_t b[4];
                int krow = ks * 16 + b_krow0;
                int colb = (wcol + n2 * 16) * 2 + b_ncol0;
                ldsm_x4_t(bbuf + SWZ(krow, colb), b);
                mma_fp16(c[0][n2 * 2 + 0], a0, b[0], b[1]);
                mma_fp16(c[0][n2 * 2 + 1], a0, b[2], b[3]);
                mma_fp16(c[1][n2 * 2 + 0], a1, b[0], b[1]);
                mma_fp16(c[1][n2 * 2 + 1], a1, b[2], b[3]);
            }
        }

        // --- epilogue: stmatrix to OUT, then coalesced copy ---
        #pragma unroll
        for (int mt = 0; mt < 2; mt++)
            #pragma unroll
            for (int h = 0; h < 2; h++) {
                uint32_t v[4];
                #pragma unroll
                for (int g = 0; g < 4; g++) {
                    __half2 hv = __floats2half2_rn(c[mt][g][h * 2], c[mt][g][h * 2 + 1]);
                    v[g] = *(uint32_t*)&hv;
                }
                stsm_x4(st_addr0 + (mt * 16 + h * 8) * 128, v[0], v[1], v[2], v[3]);
            }
        __syncthreads();   // OUT staged (all warps)

        #pragma unroll
        for (int p = 0; p < 4; p++) {
            int idx  = tid + p * 256;     // 0..1023
            int row  = idx >> 3;
            int ch16 = idx & 7;
            int gm   = m0 + row;
            if (gm < M) {
                uint4 v = *(uint4*)(smem + SM_OUT + SWZ(row, ch16 * 16));
                *(uint4*)&g_trans[(size_t)gm * NCOLS + rrel * DIM + ch16 * 8] = v;
            }
        }
        __syncthreads();   // OUT consumed; B-next fully staged
    }
}

// ---- K2: 8 lanes/edge, 2 edges per group (batched gathers for MLP), HW tanh ----
__global__ __launch_bounds__(256) void att_kernel(
    const int* __restrict__ src, const int* __restrict__ dst,
    const int* __restrict__ typ, const float* __restrict__ rel, int E)
{
    __shared__ float s_rel[NREL * DIM];
    const int tid = threadIdx.x;
    #pragma unroll
    for (int i = tid; i < NREL * DIM; i += 256) s_rel[i] = rel[i];
    __syncthreads();

    const int lane = tid & 31;
    const int grp  = lane >> 3;
    const int sub  = lane & 7;
    const int warp = (blockIdx.x * 256 + tid) >> 5;
    const int e0   = warp * 8 + grp * 2;
    const int e1   = e0 + 1;
    const bool v0 = (e0 < E), v1 = (e1 < E);

    int s0 = 0, d0 = 0, r0 = 0, s1 = 0, d1 = 0, r1 = 0;
    if (v0) { s0 = src[e0]; d0 = dst[e0]; r0 = typ[e0]; }
    if (v1) { s1 = src[e1]; d1 = dst[e1]; r1 = typ[e1]; }

    // issue all four 16B gathers before consuming (MLP=4 per lane)
    uint4 t0 = {0,0,0,0}, h0 = {0,0,0,0}, t1 = {0,0,0,0}, h1 = {0,0,0,0};
    if (v0) {
        t0 = *(const uint4*)(g_trans + (size_t)s0 * NCOLS + r0 * DIM + sub * 8);
        h0 = *(const uint4*)(g_trans + (size_t)d0 * NCOLS + r0 * DIM + sub * 8);
    }
    if (v1) {
        t1 = *(const uint4*)(g_trans + (size_t)s1 * NCOLS + r1 * DIM + sub * 8);
        h1 = *(const uint4*)(g_trans + (size_t)d1 * NCOLS + r1 * DIM + sub * 8);
    }

    float p0 = 0.0f, p1 = 0.0f;
    if (v0) {
        const float* rr = &s_rel[r0 * DIM + sub * 8];
        const uint32_t* tw = (const uint32_t*)&t0;
        const uint32_t* hw = (const uint32_t*)&h0;
        #pragma unroll
        for (int j = 0; j < 4; j++) {
            float2 tf = __half22float2(*(const __half2*)&tw[j]);
            float2 hf = __half22float2(*(const __half2*)&hw[j]);
            p0 += tf.x * tanha(hf.x + rr[2 * j]);
            p0 += tf.y * tanha(hf.y + rr[2 * j + 1]);
        }
    }
    if (v1) {
        const float* rr = &s_rel[r1 * DIM + sub * 8];
        const uint32_t* tw = (const uint32_t*)&t1;
        const uint32_t* hw = (const uint32_t*)&h1;
        #pragma unroll
        for (int j = 0; j < 4; j++) {
            float2 tf = __half22float2(*(const __half2*)&tw[j]);
            float2 hf = __half22float2(*(const __half2*)&hw[j]);
            p1 += tf.x * tanha(hf.x + rr[2 * j]);
            p1 += tf.y * tanha(hf.y + rr[2 * j + 1]);
        }
    }
    #pragma unroll
    for (int o = 1; o < 8; o <<= 1) {
        p0 += __shfl_xor_sync(0xffffffffu, p0, o);
        p1 += __shfl_xor_sync(0xffffffffu, p1, o);
    }

    if (sub == 0) {
        if (v0) {
            float ex = __expf(p0);
            g_ex[e0] = ex;
            atomicAdd(&g_denom[d0], ex);
        }
        if (v1) {
            float ex = __expf(p1);
            g_ex[e1] = ex;
            atomicAdd(&g_denom[d1], ex);
        }
    }
}

// ---- K3: normalize ----
__global__ void norm_kernel(const int* __restrict__ dst, float* __restrict__ out, int E) {
    int i = blockIdx.x * blockDim.x + threadIdx.x;
    if (i < E) out[i] = g_ex[i] / g_denom[dst[i]];
}

extern "C" void kernel_launch(void* const* d_in, const int* in_sizes, int n_in,
                              void* d_out, int out_size)
{
    const float* emb = (const float*)d_in[0];
    const float* rel = (const float*)d_in[1];
    const float* W   = (const float*)d_in[2];
    const int*   src = (const int*)d_in[3];
    const int*   dst = (const int*)d_in[4];
    const int*   typ = (const int*)d_in[5];
    float*       out = (float*)d_out;

    int M = in_sizes[0] / DIM;
    int E = in_sizes[3];

    static bool attr_set = false;
    if (!attr_set) {
        cudaFuncSetAttribute(gemm_kernel,
                             cudaFuncAttributeMaxDynamicSharedMemorySize, SM_TOT);
        attr_set = true;
    }

    gemm_kernel<<<(M + 127) / 128, 256, SM_TOT>>>(emb, W, M);
    att_kernel<<<(E + 63) / 64, 256>>>(src, dst, typ, rel, E);   // 64 edges / block
    norm_kernel<<<(E + 255) / 256, 256>>>(dst, out, E);
}